// round 1
// baseline (speedup 1.0000x reference)
#include <cuda_runtime.h>
#include <cuda_bf16.h>
#include <math_constants.h>

// Dilation2D: out[a,r] = max_{di,db in [-H,H]} input[r+di, a+db] - (di^2+db^2)/(4*scale)
// Separable parabolic dilation: two 1-D passes.
//   Pass 1: V[x,y]   = max_di input[x+di, y] - di^2/(4s)   -> stored transposed Vt[y,x]
//   Pass 2: out[a,r] = max_db Vt[a+db, r]    - db^2/(4s)
//
// K=101, H=50. Whole problem is 40KB -> L2 resident; latency-bound.

#define KK 101
#define HH (KK / 2)

__device__ float g_vt[KK * KK];   // Vt[y][x] = V[x][y]

__global__ void dil_pass1(const float* __restrict__ in,
                          const float* __restrict__ scale_p) {
    const int x = blockIdx.x;      // row index of V (input row center)
    const int y = threadIdx.x;     // column index
    if (y >= KK) return;
    const float inv = 1.0f / (4.0f * __ldg(scale_p));

    // Uniform-per-block loop bounds (no divergence within a block).
    const int dlo = -min(x, HH);
    const int dhi =  min(KK - 1 - x, HH);

    float v = -CUDART_INF_F;
    const float* col = in + y;     // stride-KK walk down the column
    #pragma unroll 4
    for (int d = dlo; d <= dhi; ++d) {
        const float ndd = -(float)(d * d);
        v = fmaxf(v, fmaf(ndd, inv, col[(x + d) * KK]));
    }
    g_vt[y * KK + x] = v;          // transposed store (scattered; 40KB total, fine)
}

__global__ void dil_pass2(const float* __restrict__ scale_p,
                          float* __restrict__ out) {
    const int a = blockIdx.x;      // output row (= input column offset axis)
    const int r = threadIdx.x;     // output column (= input row offset axis)
    if (r >= KK) return;
    const float inv = 1.0f / (4.0f * __ldg(scale_p));

    const int dlo = -min(a, HH);
    const int dhi =  min(KK - 1 - a, HH);

    float v = -CUDART_INF_F;
    const float* row = g_vt + r;   // reads Vt[(a+d)*KK + r] : coalesced across threads
    #pragma unroll 4
    for (int d = dlo; d <= dhi; ++d) {
        const float ndd = -(float)(d * d);
        v = fmaxf(v, fmaf(ndd, inv, row[(a + d) * KK]));
    }
    out[a * KK + r] = v;           // coalesced store
}

extern "C" void kernel_launch(void* const* d_in, const int* in_sizes, int n_in,
                              void* d_out, int out_size) {
    const float* in      = (const float*)d_in[0];   // (101,101) float32
    const float* scale_p = (const float*)d_in[1];   // scalar float32
    float*       out     = (float*)d_out;           // (101,101) float32

    dil_pass1<<<KK, 128>>>(in, scale_p);
    dil_pass2<<<KK, 128>>>(scale_p, out);
}

// round 3
// speedup vs baseline: 1.4681x; 1.4681x over previous
#include <cuda_runtime.h>
#include <cuda_bf16.h>
#include <math_constants.h>

// Dilation2D: out[a,r] = max_{di,db in [-H,H]} input[r+di, a+db] - (di^2+db^2)/(4*scale)
// Separable parabolic dilation, two 1-D passes:
//   Pass 1: V[x,y]   = max_di input[x+di, y] + h(di)
//   Pass 2: out[a,r] = max_db V[r, a+db]     + h(db)      h(d) = -d^2/(4s)
//
// Each block stages the FULL 40.8KB operand into smem (float4, high MLP:
// one L2-latency exposure), then runs the tap loop out of smem with 4
// independent fmax accumulators to break the dependency chain.

#define KK 101
#define HH (KK / 2)
#define NV (KK * KK)          // 10201

__device__ float g_v[NV];     // V[x*KK + y]

__device__ __forceinline__ void stage_full(const float* __restrict__ src,
                                           float* __restrict__ S) {
    // 10201 = 2550*4 + 1 ; src is 256B-aligned (cudaMalloc)
    const float4* s4 = (const float4*)src;
    float4*       d4 = (float4*)S;
    #pragma unroll
    for (int i = threadIdx.x; i < NV / 4; i += 128) d4[i] = s4[i];
    if (threadIdx.x == 0) S[NV - 1] = src[NV - 1];
    __syncthreads();
}

__device__ __forceinline__ float tap_max(const float* __restrict__ base,
                                         int stride, int dlo, int dhi,
                                         float inv) {
    float v0 = -CUDART_INF_F, v1 = -CUDART_INF_F;
    float v2 = -CUDART_INF_F, v3 = -CUDART_INF_F;
    int d = dlo;
    #pragma unroll 4
    for (; d + 3 <= dhi; d += 4) {
        v0 = fmaxf(v0, fmaf((float)(-(d    ) * (d    )), inv, base[(d    ) * stride]));
        v1 = fmaxf(v1, fmaf((float)(-(d + 1) * (d + 1)), inv, base[(d + 1) * stride]));
        v2 = fmaxf(v2, fmaf((float)(-(d + 2) * (d + 2)), inv, base[(d + 2) * stride]));
        v3 = fmaxf(v3, fmaf((float)(-(d + 3) * (d + 3)), inv, base[(d + 3) * stride]));
    }
    for (; d <= dhi; ++d)
        v0 = fmaxf(v0, fmaf((float)(-d * d), inv, base[d * stride]));
    return fmaxf(fmaxf(v0, v1), fmaxf(v2, v3));
}

__global__ __launch_bounds__(128, 1)
void dil_pass1(const float* __restrict__ in,
               const float* __restrict__ scale_p) {
    __shared__ float S[NV];
    stage_full(in, S);

    const int x = blockIdx.x;           // V row
    const int y = threadIdx.x;          // column
    if (y >= KK) return;
    const float inv = 1.0f / (4.0f * __ldg(scale_p));
    const int dlo = -min(x, HH);
    const int dhi =  min(KK - 1 - x, HH);

    // S[(x+d)*KK + y] : stride KK across d, stride 1 across threads (no conflicts)
    const float v = tap_max(S + x * KK + y, KK, dlo, dhi, inv);
    g_v[x * KK + y] = v;                // coalesced
}

__global__ __launch_bounds__(128, 1)
void dil_pass2(const float* __restrict__ scale_p,
               float* __restrict__ out) {
    __shared__ float S[NV];
    stage_full(g_v, S);

    const int a = blockIdx.x;           // output row
    const int r = threadIdx.x;          // output column
    if (r >= KK) return;
    const float inv = 1.0f / (4.0f * __ldg(scale_p));
    const int dlo = -min(a, HH);
    const int dhi =  min(KK - 1 - a, HH);

    // S[r*KK + a+d] : stride 1 across d, stride KK (=5 banks, odd) across threads
    const float v = tap_max(S + r * KK + a, 1, dlo, dhi, inv);
    out[a * KK + r] = v;                // coalesced
}

extern "C" void kernel_launch(void* const* d_in, const int* in_sizes, int n_in,
                              void* d_out, int out_size) {
    const float* in      = (const float*)d_in[0];   // (101,101) float32
    const float* scale_p = (const float*)d_in[1];   // scalar float32
    float*       out     = (float*)d_out;           // (101,101) float32

    dil_pass1<<<KK, 128>>>(in, scale_p);
    dil_pass2<<<KK, 128>>>(scale_p, out);
}

// round 4
// speedup vs baseline: 1.5398x; 1.0488x over previous
#include <cuda_runtime.h>
#include <cuda_bf16.h>
#include <math_constants.h>

// Dilation2D: out[a,r] = max_{di,db in [-H,H]} input[r+di, a+db] - (di^2+db^2)/(4*scale)
// Separable parabolic dilation FUSED into one launch:
//   phase 1: V[x,y]   = max_di input[x+di, y] + h(di)     (block x)
//   -- software grid barrier (all 101 blocks co-resident: 101 < 148 SMs) --
//   phase 2: out[a,r] = max_db V[r, a+db]     + h(db)     (block a)
// h(d) = -d^2/(4s). Each phase stages the full 40.8KB operand into smem.

#define KK 101
#define HH (KK / 2)
#define NV (KK * KK)          // 10201
#define NBLK KK

__device__ float g_v[NV];                 // V[x*KK + y]
__device__ unsigned g_bar = 0;            // monotone ticket counter (replay-safe)

__device__ __forceinline__ void stage_full(const float* __restrict__ src,
                                           float* __restrict__ S) {
    const float4* s4 = (const float4*)src;
    float4*       d4 = (float4*)S;
    #pragma unroll
    for (int i = threadIdx.x; i < NV / 4; i += 128) d4[i] = s4[i];
    if (threadIdx.x == 0) S[NV - 1] = src[NV - 1];
    __syncthreads();
}

__device__ __forceinline__ float tap_max(const float* __restrict__ base,
                                         int stride, int dlo, int dhi,
                                         float inv) {
    float v0 = -CUDART_INF_F, v1 = -CUDART_INF_F;
    float v2 = -CUDART_INF_F, v3 = -CUDART_INF_F;
    int d = dlo;
    #pragma unroll 4
    for (; d + 3 <= dhi; d += 4) {
        v0 = fmaxf(v0, fmaf((float)(-(d    ) * (d    )), inv, base[(d    ) * stride]));
        v1 = fmaxf(v1, fmaf((float)(-(d + 1) * (d + 1)), inv, base[(d + 1) * stride]));
        v2 = fmaxf(v2, fmaf((float)(-(d + 2) * (d + 2)), inv, base[(d + 2) * stride]));
        v3 = fmaxf(v3, fmaf((float)(-(d + 3) * (d + 3)), inv, base[(d + 3) * stride]));
    }
    for (; d <= dhi; ++d)
        v0 = fmaxf(v0, fmaf((float)(-d * d), inv, base[d * stride]));
    return fmaxf(fmaxf(v0, v1), fmaxf(v2, v3));
}

__global__ __launch_bounds__(128, 1)
void dil_fused(const float* __restrict__ in,
               const float* __restrict__ scale_p,
               float* __restrict__ out) {
    __shared__ float S[NV];
    const int b = blockIdx.x;       // row index for both phases
    const int t = threadIdx.x;
    const float inv = 1.0f / (4.0f * __ldg(scale_p));

    // ---------- phase 1: vertical parabolic dilation ----------
    stage_full(in, S);
    const int dlo = -min(b, HH);
    const int dhi =  min(KK - 1 - b, HH);
    if (t < KK) {
        // S[(b+d)*KK + t] : stride-1 across threads (conflict-free)
        const float v = tap_max(S + b * KK + t, KK, dlo, dhi, inv);
        g_v[b * KK + t] = v;         // coalesced
    }

    // ---------- grid barrier (all blocks co-resident) ----------
    __threadfence();                 // make g_v[b,:] visible GPU-wide
    __syncthreads();                 // all warps' stores issued before arrival
    if (t == 0) {
        const unsigned ticket = atomicAdd(&g_bar, 1u) + 1u;
        // round ticket up to next multiple of NBLK: same target for all
        // blocks of this launch; monotone across graph replays (no reset).
        const unsigned target = ((ticket + NBLK - 1u) / NBLK) * NBLK;
        while (*(volatile unsigned*)&g_bar < target) { }
    }
    __syncthreads();
    __threadfence();                 // acquire: order g_v reads after spin

    // ---------- phase 2: horizontal parabolic dilation ----------
    stage_full(g_v, S);
    if (t < KK) {
        // S[t*KK + b+d] : stride-1 across d; stride-101 across threads (odd -> conflict-free)
        const float v = tap_max(S + t * KK + b, 1, dlo, dhi, inv);
        out[b * KK + t] = v;         // coalesced
    }
}

extern "C" void kernel_launch(void* const* d_in, const int* in_sizes, int n_in,
                              void* d_out, int out_size) {
    const float* in      = (const float*)d_in[0];   // (101,101) float32
    const float* scale_p = (const float*)d_in[1];   // scalar float32
    float*       out     = (float*)d_out;           // (101,101) float32

    dil_fused<<<NBLK, 128>>>(in, scale_p, out);
}

// round 5
// speedup vs baseline: 2.2950x; 1.4904x over previous
#include <cuda_runtime.h>
#include <cuda_bf16.h>
#include <math_constants.h>

// Dilation2D: out[a,r] = max_{di,db in [-H,H]} input[r+di, a+db] - (di^2+db^2)/(4*scale)
// Separable, reordered so each block is fully independent (NO grid barrier):
//   Block j:
//     phase 1: V[y]    = max_di input[j+di, y] + h(di)    (reads input straight from L2)
//     phase 2: out[a,j]= max_db V[a+db]        + h(db)    (block-local V, -inf padded)
//   h(d) = -d^2/(4s).
// 512 threads = 4 warp-groups; each 101-tap reduction is split 4 ways across
// groups (16 warps/SM hide all latency), combined via smem partials.

#define KK 101
#define HH (KK / 2)
#define NT 512

__global__ __launch_bounds__(NT, 1)
void dil_fused(const float* __restrict__ in,
               const float* __restrict__ scale_p,
               float* __restrict__ out) {
    __shared__ float P[4][128];            // per-group partial maxima
    __shared__ float V[KK + 2 * HH];       // padded V row (201 floats)

    const int j = blockIdx.x;              // V row == output column
    const int t = threadIdx.x;
    const int q = t >> 7;                  // warp-group 0..3 (uniform per warp)
    const int y = t & 127;                 // lane-position 0..127
    const float inv = 1.0f / (4.0f * __ldg(scale_p));

    // -inf padding (middle overwritten after sync1)
    for (int i = t; i < KK + 2 * HH; i += NT) V[i] = -CUDART_INF_F;

    // ---------- phase 1: V[y] = max_d in[(j+d)*KK + y] + h(d), split over q ----------
    const int dlo = -min(j, HH);
    const int dhi =  min(KK - 1 - j, HH);
    const int n   = dhi - dlo + 1;
    const int c0  = dlo + (n * q)       / 4;
    const int c1  = dlo + (n * (q + 1)) / 4;   // exclusive

    float v = -CUDART_INF_F;
    if (y < KK) {
        const float* col = in + j * KK + y;    // coalesced across y
        #pragma unroll 4
        for (int d = c0; d < c1; ++d)
            v = fmaxf(v, fmaf((float)(-d * d), inv, col[d * KK]));
    }
    P[q][y] = v;
    __syncthreads();
    if (q == 0 && y < KK)
        V[HH + y] = fmaxf(fmaxf(P[0][y], P[1][y]), fmaxf(P[2][y], P[3][y]));
    __syncthreads();

    // ---------- phase 2: out[a,j] = max_d V[HH + a + d] + h(d), d in [-HH,HH] ----------
    const int e0 = -HH + (KK * q)       / 4;
    const int e1 = -HH + (KK * (q + 1)) / 4;

    float w = -CUDART_INF_F;
    if (y < KK) {
        const float* vb = V + HH + y;          // lanes consecutive: conflict-free LDS
        #pragma unroll 4
        for (int d = e0; d < e1; ++d)
            w = fmaxf(w, fmaf((float)(-d * d), inv, vb[d]));
    }
    __syncthreads();                            // P safe to reuse (readers done at sync above)
    P[q][y] = w;
    __syncthreads();
    if (q == 0 && y < KK)
        out[y * KK + j] =
            fmaxf(fmaxf(P[0][y], P[1][y]), fmaxf(P[2][y], P[3][y]));
}

extern "C" void kernel_launch(void* const* d_in, const int* in_sizes, int n_in,
                              void* d_out, int out_size) {
    const float* in      = (const float*)d_in[0];   // (101,101) float32
    const float* scale_p = (const float*)d_in[1];   // scalar float32
    float*       out     = (float*)d_out;           // (101,101) float32

    dil_fused<<<KK, NT>>>(in, scale_p, out);
}

// round 8
// speedup vs baseline: 2.7227x; 1.1864x over previous
#include <cuda_runtime.h>
#include <cuda_bf16.h>
#include <math_constants.h>

// Dilation2D: out[a,r] = max_{di,db in [-H,H]} input[r+di, a+db] - (di^2+db^2)/(4*scale)
// Separable, block j fully independent:
//   phase 1: V[y]     = max_di input[j+di, y] + h(di)   (L2-direct, branch-free clamped loads)
//   phase 2: out[a,j] = max_db V[a+db]        + h(db)   (smem V, -inf padded)
// 512 threads = 4 warp-groups; each group owns a FIXED 26-tap slice
// (compile-time unroll -> all 26 LDGs in flight at once, one L2 exposure).
// R7 fix: phase-2 smem base must use clamped yc (y up to 127 + d up to 53
// overran the old 208-float pad -> illegal address). VPAD 256 for slack.

#define KK 101
#define HH (KK / 2)
#define NT 512
#define TAPS 26                 // 4*26 = 104 >= 101 taps; extras predicated off
#define VPAD 256                // max smem index: HH + 100 + 53 = 203 < 256

__global__ __launch_bounds__(NT, 1)
void dil_fused(const float* __restrict__ in,
               const float* __restrict__ scale_p,
               float* __restrict__ out) {
    __shared__ float P[4][128];         // per-group partials
    __shared__ float V[VPAD];           // padded V row

    const int j  = blockIdx.x;          // V row == output column
    const int t  = threadIdx.x;
    const int q  = t >> 7;              // warp-group 0..3
    const int y  = t & 127;             // lane position 0..127
    const int yc = min(y, KK - 1);      // clamped (all accesses legal)
    const float inv = 1.0f / (4.0f * __ldg(scale_p));

    for (int i = t; i < VPAD; i += NT) V[i] = -CUDART_INF_F;

    // ---------- phase 1: 26 fixed taps per group, fully unrolled ----------
    const int dbase = -HH + TAPS * q;
    const float* col = in + yc;
    float a0 = -CUDART_INF_F, a1 = -CUDART_INF_F;
    float a2 = -CUDART_INF_F, a3 = -CUDART_INF_F;
    #pragma unroll
    for (int i = 0; i < TAPS; ++i) {
        const int d   = dbase + i;
        const int row = j + d;
        const bool ok = (d <= HH) && ((unsigned)row < (unsigned)KK);
        const int  rc = min(max(row, 0), KK - 1);
        const float x = __ldg(col + rc * KK);             // coalesced, always legal
        const float cand = ok ? fmaf((float)(-d * d), inv, x) : -CUDART_INF_F;
        switch (i & 3) {
            case 0: a0 = fmaxf(a0, cand); break;
            case 1: a1 = fmaxf(a1, cand); break;
            case 2: a2 = fmaxf(a2, cand); break;
            default: a3 = fmaxf(a3, cand); break;
        }
    }
    P[q][y] = fmaxf(fmaxf(a0, a1), fmaxf(a2, a3));
    __syncthreads();
    if (q == 0 && y < KK)
        V[HH + y] = fmaxf(fmaxf(P[0][y], P[1][y]), fmaxf(P[2][y], P[3][y]));
    __syncthreads();

    // ---------- phase 2: 26 fixed taps per group from smem (padding kills OOR) ----------
    const float* vb = V + HH + yc;      // clamped base: max index 203 < VPAD
    float b0 = -CUDART_INF_F, b1 = -CUDART_INF_F;
    float b2 = -CUDART_INF_F, b3 = -CUDART_INF_F;
    #pragma unroll
    for (int i = 0; i < TAPS; ++i) {
        const int d = dbase + i;
        const float cand = fmaf((float)(-d * d), inv, vb[d]);   // -inf pad absorbs OOR
        switch (i & 3) {
            case 0: b0 = fmaxf(b0, cand); break;
            case 1: b1 = fmaxf(b1, cand); break;
            case 2: b2 = fmaxf(b2, cand); break;
            default: b3 = fmaxf(b3, cand); break;
        }
    }
    __syncthreads();                    // P reuse safe
    P[q][y] = fmaxf(fmaxf(b0, b1), fmaxf(b2, b3));
    __syncthreads();
    if (q == 0 && y < KK)
        out[y * KK + j] = fmaxf(fmaxf(P[0][y], P[1][y]), fmaxf(P[2][y], P[3][y]));
}

extern "C" void kernel_launch(void* const* d_in, const int* in_sizes, int n_in,
                              void* d_out, int out_size) {
    const float* in      = (const float*)d_in[0];   // (101,101) float32
    const float* scale_p = (const float*)d_in[1];   // scalar float32
    float*       out     = (float*)d_out;           // (101,101) float32

    dil_fused<<<KK, NT>>>(in, scale_p, out);
}